// round 7
// baseline (speedup 1.0000x reference)
#include <cuda_runtime.h>
#include <cstdint>

// SpatialCorrelationSampler via warp-level mma.sync bf16 (hi/lo split, fp32 acc).
// out[b, dy*9+dx, h, w] = sum_c in1[b,c,h,w] * in2_zp4[b,c,h+dy,w+dx]
// in1,in2: (4,256,128,128) fp32; out: (4,81,128,128) fp32.
//
// Per block: tile 16w x 8h (M=128 px), halo 24w x 16h (N=384), K=256.
// D[p][q] = sum_k A[p][k]*B[q][k]. bf16 split: 3 MMA products per step.
// 8 warps; warp (pt, half) owns 32 px (2 h-rows) x 5 halo rows x 24 -> 120 acc regs.

namespace {

constexpr int C = 256, H = 128, W = 128, PATCH = 9, PAD = 4;
constexpr int HW = H * W;
constexpr int TW = 16, TH = 8;
constexpr int CCH = 32, NCHUNK = C / CCH;        // 8

constexpr int A_STRIDE = 272;                    // 128 px *2B + 16 pad
constexpr int A_PLANE  = 32 * A_STRIDE;          // 8704
constexpr int B_STRIDE = 784;                    // 384 px *2B + 16 pad
constexpr int B_PLANE  = 32 * B_STRIDE;          // 25088
constexpr int B_BASE   = 2 * A_PLANE;            // 17408
constexpr int STAGE_BYTES = B_BASE + 2 * B_PLANE;// 67584
constexpr int EPI_BYTES = 128 * 10 * 24 * 4;     // 122880
constexpr int DYN_BYTES = EPI_BYTES;             // > STAGE_BYTES

// ---------------- PTX wrappers (all baseline ISA) --------------------------
__device__ __forceinline__ void ldsm_x4t(uint32_t* f, uint32_t addr) {
    asm volatile("ldmatrix.sync.aligned.m8n8.x4.trans.shared.b16 "
                 "{%0,%1,%2,%3}, [%4];"
                 : "=r"(f[0]), "=r"(f[1]), "=r"(f[2]), "=r"(f[3]) : "r"(addr));
}
__device__ __forceinline__ void ldsm_x2t(uint32_t& f0, uint32_t& f1, uint32_t addr) {
    asm volatile("ldmatrix.sync.aligned.m8n8.x2.trans.shared.b16 "
                 "{%0,%1}, [%2];"
                 : "=r"(f0), "=r"(f1) : "r"(addr));
}
__device__ __forceinline__ void mma_bf16(float* d, const uint32_t* a,
                                         uint32_t b0, uint32_t b1) {
    asm volatile("mma.sync.aligned.m16n8k16.row.col.f32.bf16.bf16.f32 "
                 "{%0,%1,%2,%3}, {%4,%5,%6,%7}, {%8,%9}, {%0,%1,%2,%3};"
                 : "+f"(d[0]), "+f"(d[1]), "+f"(d[2]), "+f"(d[3])
                 : "r"(a[0]), "r"(a[1]), "r"(a[2]), "r"(a[3]), "r"(b0), "r"(b1));
}
// pack: v1 -> upper bf16, v0 -> lower bf16
__device__ __forceinline__ uint32_t cvt_bf16x2(float v1, float v0) {
    uint32_t r;
    asm("cvt.rn.bf16x2.f32 %0, %1, %2;" : "=r"(r) : "f"(v1), "f"(v0));
    return r;
}
// hi/lo split of a value pair (v0 = lower lane of the b32 word)
__device__ __forceinline__ void split2(float v0, float v1,
                                       uint32_t& hi, uint32_t& lo) {
    hi = cvt_bf16x2(v1, v0);
    float h0 = __uint_as_float(hi << 16);
    float h1 = __uint_as_float(hi & 0xFFFF0000u);
    lo = cvt_bf16x2(v1 - h1, v0 - h0);
}

__global__ __launch_bounds__(256, 1)
void corr_mma_kernel(const float* __restrict__ in1,
                     const float* __restrict__ in2,
                     float* __restrict__ out) {
    extern __shared__ char sm[];
    const uint32_t smb = (uint32_t)__cvta_generic_to_shared(sm);

    const int tid  = threadIdx.x;
    const int warp = tid >> 5;
    const int lane = tid & 31;
    const int b  = blockIdx.z;
    const int w0 = blockIdx.x * TW;
    const int h0 = blockIdx.y * TH;

    // ---------------- conversion-role state --------------------------------
    const int ck  = tid >> 3;   // channel within chunk, 0..31
    const int cs  = tid & 7;    // A: h-row 0..7; B: row-pair segment 0..7
    const float* aptr = in1 + ((size_t)(b * C + ck) * H + (h0 + cs)) * W + w0;
    const int gy0 = h0 + 2 * cs - PAD, gy1 = gy0 + 1;
    const bool ry0 = (gy0 >= 0 && gy0 < H);
    const bool ry1 = (gy1 >= 0 && gy1 < H);
    const float* bptr0 = in2 + ((size_t)(b * C + ck) * H + (ry0 ? gy0 : 0)) * W + (w0 - PAD);
    const float* bptr1 = in2 + ((size_t)(b * C + ck) * H + (ry1 ? gy1 : 0)) * W + (w0 - PAD);
    const bool x0ok = (w0 > 0), x5ok = (w0 < 112);
    const float4 zero4 = make_float4(0.f, 0.f, 0.f, 0.f);

    // ---------------- MMA-role state ---------------------------------------
    const int pt = warp >> 1, half = warp & 1;
    const int p0 = pt * 32;
    const int rg0 = 2 * pt + 5 * half;                      // halo row base
    const uint32_t a_row = (uint32_t)(((lane >> 4) * 8 + (lane & 7)));
    const uint32_t a_px8 = (uint32_t)(((lane >> 3) & 1) * 8);
    const uint32_t b_row = (uint32_t)((((lane >> 3) & 1) * 8 + (lane & 7)));

    float acc[5][3][2][4];
#pragma unroll
    for (int r = 0; r < 5; ++r)
#pragma unroll
        for (int n = 0; n < 3; ++n)
#pragma unroll
            for (int m = 0; m < 2; ++m)
#pragma unroll
                for (int q = 0; q < 4; ++q) acc[r][n][m][q] = 0.f;

    // ---------------- main loop over K chunks ------------------------------
#pragma unroll 1
    for (int k = 0; k < NCHUNK; ++k) {
        // --- global loads (no smem hazard; overlaps other warps' MMA) ---
        float4 va[4];
#pragma unroll
        for (int j = 0; j < 4; ++j) va[j] = __ldg((const float4*)aptr + j);
        float4 vb[2][6];
#pragma unroll
        for (int j = 0; j < 6; ++j) {
            bool xok = (j == 0) ? x0ok : ((j == 5) ? x5ok : true);
            vb[0][j] = (ry0 && xok) ? __ldg((const float4*)bptr0 + j) : zero4;
            vb[1][j] = (ry1 && xok) ? __ldg((const float4*)bptr1 + j) : zero4;
        }
        aptr += CCH * HW; bptr0 += CCH * HW; bptr1 += CCH * HW;

        __syncthreads();   // previous chunk's MMA done reading stage

        // --- convert + STS: A plane [k][px], hi then lo ---
        {
            uint32_t hi[8], lo[8];
#pragma unroll
            for (int j = 0; j < 4; ++j) {
                split2(va[j].x, va[j].y, hi[2 * j],     lo[2 * j]);
                split2(va[j].z, va[j].w, hi[2 * j + 1], lo[2 * j + 1]);
            }
            char* ab = sm + ck * A_STRIDE + cs * 32;
            *(uint4*)(ab)                = make_uint4(hi[0], hi[1], hi[2], hi[3]);
            *(uint4*)(ab + 16)           = make_uint4(hi[4], hi[5], hi[6], hi[7]);
            *(uint4*)(ab + A_PLANE)      = make_uint4(lo[0], lo[1], lo[2], lo[3]);
            *(uint4*)(ab + A_PLANE + 16) = make_uint4(lo[4], lo[5], lo[6], lo[7]);
        }
        // --- convert + STS: B planes, two halo rows ---
#pragma unroll
        for (int rr = 0; rr < 2; ++rr) {
            const float4* vr = vb[rr];
            float v[24];
#pragma unroll
            for (int j = 0; j < 6; ++j) {
                v[4 * j] = vr[j].x; v[4 * j + 1] = vr[j].y;
                v[4 * j + 2] = vr[j].z; v[4 * j + 3] = vr[j].w;
            }
            uint32_t hi[12], lo[12];
#pragma unroll
            for (int m = 0; m < 12; ++m) split2(v[2 * m], v[2 * m + 1], hi[m], lo[m]);
            char* bb = sm + B_BASE + ck * B_STRIDE + (cs * 2 + rr) * 48;
            *(uint4*)(bb)                = make_uint4(hi[0], hi[1], hi[2],  hi[3]);
            *(uint4*)(bb + 16)           = make_uint4(hi[4], hi[5], hi[6],  hi[7]);
            *(uint4*)(bb + 32)           = make_uint4(hi[8], hi[9], hi[10], hi[11]);
            *(uint4*)(bb + B_PLANE)      = make_uint4(lo[0], lo[1], lo[2],  lo[3]);
            *(uint4*)(bb + B_PLANE + 16) = make_uint4(lo[4], lo[5], lo[6],  lo[7]);
            *(uint4*)(bb + B_PLANE + 32) = make_uint4(lo[8], lo[9], lo[10], lo[11]);
        }

        __syncthreads();   // stage ready for MMA

        // --- MMA phase ---
#pragma unroll
        for (int ks = 0; ks < 2; ++ks) {
            uint32_t Ah[2][4], Al[2][4];
#pragma unroll
            for (int mt = 0; mt < 2; ++mt) {
                uint32_t aaddr = smb + (ks * 16 + a_row) * A_STRIDE
                               + (uint32_t)(p0 + mt * 16) * 2 + a_px8 * 2;
                ldsm_x4t(Ah[mt], aaddr);
                ldsm_x4t(Al[mt], aaddr + A_PLANE);
            }
#pragma unroll
            for (int r = 0; r < 5; ++r) {
                const int hr = rg0 + r;
#pragma unroll
                for (int nt = 0; nt < 3; ++nt) {
                    uint32_t baddr = smb + B_BASE + (ks * 16 + b_row) * B_STRIDE
                                   + (uint32_t)(hr * 24 + nt * 8) * 2;
                    uint32_t bh0, bh1, bl0, bl1;
                    ldsm_x2t(bh0, bh1, baddr);
                    ldsm_x2t(bl0, bl1, baddr + B_PLANE);
                    // interleave mt to break RAW chains on acc
                    mma_bf16(acc[r][nt][0], Ah[0], bh0, bh1);
                    mma_bf16(acc[r][nt][1], Ah[1], bh0, bh1);
                    mma_bf16(acc[r][nt][0], Ah[0], bl0, bl1);
                    mma_bf16(acc[r][nt][1], Ah[1], bl0, bl1);
                    mma_bf16(acc[r][nt][0], Al[0], bh0, bh1);
                    mma_bf16(acc[r][nt][1], Al[1], bh0, bh1);
                }
            }
        }
    }

    // ---------------- epilogue ---------------------------------------------
    __syncthreads();            // all MMA smem reads done; stage is dead
    float* epi = (float*)sm;    // [p 0..127][r_loc 0..9][wx 0..23]

    {
        const int rowp = lane >> 2;
        const int wxl  = (lane & 3) * 2;
#pragma unroll
        for (int r = 0; r < 5; ++r) {
            const int rl = half * 5 + r;
#pragma unroll
            for (int nt = 0; nt < 3; ++nt) {
                const int wx = nt * 8 + wxl;
#pragma unroll
                for (int mt = 0; mt < 2; ++mt) {
                    const float* d = acc[r][nt][mt];
                    const int p = p0 + mt * 16 + rowp;
                    *(float2*)&epi[(p * 10 + rl) * 24 + wx] =
                        make_float2(d[0], d[1]);
                    *(float2*)&epi[((p + 8) * 10 + rl) * 24 + wx] =
                        make_float2(d[2], d[3]);
                }
            }
        }
    }
    __syncthreads();

    // gather: 648 output rows of 16 floats, fully coalesced float4 stores
    for (int i = tid; i < TH * PATCH * PATCH; i += 256) {
        const int hp = i / 81, rem = i % 81;
        const int dy = rem / 9, dx = rem % 9;
        const int rl = (hp & 1) + dy;
        float v[16];
#pragma unroll
        for (int wp = 0; wp < 16; ++wp)
            v[wp] = epi[((hp * 16 + wp) * 10 + rl) * 24 + wp + dx];
        float* op = out + (((size_t)b * (PATCH * PATCH) + dy * PATCH + dx) * H
                           + (h0 + hp)) * W + w0;
        *(float4*)(op)      = make_float4(v[0],  v[1],  v[2],  v[3]);
        *(float4*)(op + 4)  = make_float4(v[4],  v[5],  v[6],  v[7]);
        *(float4*)(op + 8)  = make_float4(v[8],  v[9],  v[10], v[11]);
        *(float4*)(op + 12) = make_float4(v[12], v[13], v[14], v[15]);
    }
}

}  // namespace

extern "C" void kernel_launch(void* const* d_in, const int* in_sizes, int n_in,
                              void* d_out, int out_size) {
    const float* in1 = (const float*)d_in[0];
    const float* in2 = (const float*)d_in[1];
    float* out = (float*)d_out;

    cudaFuncSetAttribute(corr_mma_kernel,
                         cudaFuncAttributeMaxDynamicSharedMemorySize,
                         DYN_BYTES);

    int B = in_sizes[0] / (C * H * W);          // 4
    dim3 grid(W / TW, H / TH, B);               // (8, 16, 4) = 512
    corr_mma_kernel<<<grid, 256, DYN_BYTES>>>(in1, in2, out);
}